// round 16
// baseline (speedup 1.0000x reference)
#include <cuda_runtime.h>
#include <stdint.h>

// Problem constants
#define NC   14
#define NB   2
#define HH   96
#define WW   96
#define DDim 96
#define CS   (HH*WW*DDim)      // class stride = 884736
#define CS4  (CS/4)
#define ROW  (WW*DDim)         // 9216 floats per h-slice

// Tiling: block (24,8) = 192 threads, 4 voxels/thread (float4), TD = full d
#define TD   96
#define TW   8
#define HCH  4
#define NS   (HCH+2)           // 6 label slices resident
#define SW   (TW+2)            // 10
#define SD   (TD+2)            // 98 shorts per row (even -> 4B-aligned rows)
#define SDU  49                // uints per row
#define CELLS (SW*SD)          // 980 shorts per slice
#define CELLSU (CELLS/2)       // 490 uints per slice
#define GRID_TOTAL 576

__device__ double             g_num[NB*NC];
__device__ unsigned long long g_cnt[NB*NC];
__device__ unsigned           g_done;

__device__ __forceinline__ void l2_prefetch(const void* p) {
    asm volatile("prefetch.global.L2 [%0];" :: "l"(p));
}

__global__ void __launch_bounds__(192, 4) bkd_kernel(
    const float* __restrict__ pS,
    const float* __restrict__ pT,
    const int*   __restrict__ lab,
    float*       __restrict__ out)
{
    const int tx  = threadIdx.x;          // 0..23 (d quad)
    const int ty  = threadIdx.y;          // 0..7  (w)
    const int tid = ty*24 + tx;
    const int w0  = blockIdx.y * TW;
    const int bz  = blockIdx.z;           // 0..47
    const int b   = bz & 1;
    const int h0  = (bz >> 1) * HCH;

    __shared__ unsigned short sm[NS*CELLS];     // 11760 B
    __shared__ int s_is32;

    // ---- label dtype detection (int64 vs int32 layout)
    if (tid == 0) s_is32 = 0;
    __syncthreads();
    if (tid < 128) {
        int odd = lab[2*tid + 1] | lab[2*tid + 257];
        unsigned bal = __ballot_sync(0xffffffffu, odd != 0);
        if (bal && (tid & 31) == 0) atomicOr(&s_is32, 1);
    }
    __syncthreads();
    const int shift = s_is32 ? 0 : 1;

    // ---- prologue: load ALL label slices for this chunk into smem
    for (int c = tid; c < NS*CELLS; c += 192) {
        int sl  = c / CELLS;
        int rem = c - sl*CELLS;
        int wi  = rem / SD;
        int di  = rem - wi*SD;
        int gh = h0 - 1 + sl, gw = w0 - 1 + wi, gd = di - 1;
        unsigned short v = 0;
        if ((unsigned)gh < HH && (unsigned)gw < WW && (unsigned)gd < DDim) {
            int L = __ldg(lab + ((((b*HH + gh)*WW + gw)*DDim + gd) << shift));
            v = (unsigned short)(1u << L);
        }
        sm[c] = v;
    }
    __syncthreads();

    const int dv0 = 4*tx;
    const int w   = w0 + ty;
    const unsigned* smu = (const unsigned*)sm;

    float    acc[NC];
    unsigned cntp[4];                     // 8-bit fields, classes 4j..4j+3 (max 16)
#pragma unroll
    for (int k = 0; k < NC; ++k) acc[k] = 0.f;
#pragma unroll
    for (int j = 0; j < 4; ++j) cntp[j] = 0u;

    const bool w_in = (w >= 1) && (w <= WW-2);
    const bool di0  = (dv0 >= 1);                      // tx=0 -> false
    const bool di3  = (dv0+3 <= DDim-2);               // tx=23 -> false

    // hoisted streaming base (advance by ROW/4 float4 per h-step)
    const float4* ps4 = (const float4*)(pS + ((b*NC*HH + h0)*WW + w)*DDim + dv0);
    const float4* pt4 = (const float4*)(pT + ((b*NC*HH + h0)*WW + w)*DDim + dv0);

    for (int i = 0; i < HCH; ++i) {
        const int h = h0 + i;

        // ---- L2 prefetch next h-step's 28 streams (distance-1)
        if (i < HCH - 1) {
#pragma unroll
            for (int c = 0; c < NC; ++c) {
                l2_prefetch(ps4 + c*CS4 + ROW/4);
                l2_prefetch(pt4 + c*CS4 + ROW/4);
            }
        }

        // ---- KL over classes for 4 voxels (float4 streams)
        float sS0=0.f,sS1=0.f,sS2=0.f,sS3=0.f;
        float sT0=0.f,sT1=0.f,sT2=0.f,sT3=0.f;
        float n0=0.f,n1=0.f,n2=0.f,n3=0.f;
#pragma unroll
        for (int c = 0; c < NC; ++c) {
            float4 s = __ldcs(ps4 + c*CS4);
            float4 t = __ldcs(pt4 + c*CS4);
            float e0=__expf(t.x), e1=__expf(t.y), e2=__expf(t.z), e3=__expf(t.w);
            sT0+=e0; sT1+=e1; sT2+=e2; sT3+=e3;
            n0=fmaf(e0,t.x-s.x,n0); n1=fmaf(e1,t.y-s.y,n1);
            n2=fmaf(e2,t.z-s.z,n2); n3=fmaf(e3,t.w-s.w,n3);
            sS0+=__expf(s.x); sS1+=__expf(s.y); sS2+=__expf(s.z); sS3+=__expf(s.w);
        }
        float r0=__fdividef(1.f,sT0), r1=__fdividef(1.f,sT1);
        float r2=__fdividef(1.f,sT2), r3=__fdividef(1.f,sT3);
        float kl0 = fmaf(n0, r0, __logf(sS0*r0));
        float kl1 = fmaf(n1, r1, __logf(sS1*r1));
        float kl2 = fmaf(n2, r2, __logf(sS2*r2));
        float kl3 = fmaf(n3, r3, __logf(sS3*r3));
        ps4 += ROW/4;
        pt4 += ROW/4;

        // ---- 26-neighbor presence masks, aligned uint32 window reads
        // voxels (dv0..dv0+3) = halo shorts (4tx+1..4tx+4); window shorts
        // 4tx..4tx+5 = uints 2tx, 2tx+1, 2tx+2 (rows 4B-aligned, SD even)
        unsigned A0=0, A1=0, A2=0, C0, C1, C2;
#pragma unroll
        for (int r = 0; r < 3; ++r) {
            const unsigned* p = smu + i*CELLSU + (ty + r)*SDU + 2*tx;   // slice h-1
            A0 |= p[0]; A1 |= p[1]; A2 |= p[2];
            const unsigned* q = p + 2*CELLSU;                            // slice h+1
            A0 |= q[0]; A1 |= q[1]; A2 |= q[2];
        }
        {
            const unsigned* p = smu + (i+1)*CELLSU + ty*SDU + 2*tx;      // slice h, w-1
            A0 |= p[0]; A1 |= p[1]; A2 |= p[2];
            const unsigned* q = p + 2*SDU;                               // w+1
            A0 |= q[0]; A1 |= q[1]; A2 |= q[2];
            const unsigned* cc = p + SDU;                                // center row
            C0 = cc[0]; C1 = cc[1]; C2 = cc[2];
        }
        unsigned a0=A0&0xffffu, a1=A0>>16, a2=A1&0xffffu, a3=A1>>16, a4=A2&0xffffu, a5=A2>>16;
        unsigned c0=C0&0xffffu, c1=C0>>16, c2=C1&0xffffu, c3=C1>>16, c4=C2&0xffffu, c5=C2>>16;
        unsigned m0 = a0|a1|a2|c0|c2;
        unsigned m1 = a1|a2|a3|c1|c3;
        unsigned m2 = a2|a3|a4|c2|c4;
        unsigned m3 = a3|a4|a5|c3|c5;

        const bool hw = w_in && (h >= 1) && (h <= HH-2);
        unsigned bm0 = (hw && di0 && ((m0&(m0-1u))==0u)) ? 0u : m0;
        unsigned bm1 = (hw &&        ((m1&(m1-1u))==0u)) ? 0u : m1;
        unsigned bm2 = (hw &&        ((m2&(m2-1u))==0u)) ? 0u : m2;
        unsigned bm3 = (hw && di3 && ((m3&(m3-1u))==0u)) ? 0u : m3;

#pragma unroll
        for (int k = 0; k < NC; ++k) {
            const unsigned bit = 1u << k;
            const unsigned fld = 1u << (8*(k & 3));
            if (bm0 & bit) { acc[k] += kl0; cntp[k >> 2] += fld; }
            if (bm1 & bit) { acc[k] += kl1; cntp[k >> 2] += fld; }
            if (bm2 & bit) { acc[k] += kl2; cntp[k >> 2] += fld; }
            if (bm3 & bit) { acc[k] += kl3; cntp[k >> 2] += fld; }
        }
    }

    // ---- expand 8-bit counters (max 16 < 255), then warp-reduce
    int cnt[NC];
#pragma unroll
    for (int k = 0; k < NC; ++k)
        cnt[k] = (int)((cntp[k >> 2] >> (8*(k & 3))) & 0xffu);

#pragma unroll
    for (int k = 0; k < NC; ++k) {
        float a = acc[k]; int c = cnt[k];
#pragma unroll
        for (int off = 16; off; off >>= 1) {
            a += __shfl_xor_sync(0xffffffffu, a, off);
            c += __shfl_xor_sync(0xffffffffu, c, off);
        }
        acc[k] = a; cnt[k] = c;
    }

    __shared__ float rf[NC];
    __shared__ int   ri[NC];
    if (tid < NC) { rf[tid] = 0.f; ri[tid] = 0; }
    __syncthreads();
    if ((tid & 31) == 0) {
#pragma unroll
        for (int k = 0; k < NC; ++k) {
            atomicAdd(&rf[k], acc[k]);
            atomicAdd(&ri[k], cnt[k]);
        }
    }
    __syncthreads();
    if (tid < NC) {
        atomicAdd(&g_num[b*NC + tid], (double)rf[tid]);
        atomicAdd(&g_cnt[b*NC + tid], (unsigned long long)ri[tid]);
    }

    // ---- last-block finalize (fused epilogue)
    __threadfence();
    __shared__ int isLast;
    if (tid == 0) isLast = (atomicAdd(&g_done, 1u) == GRID_TOTAL - 1u) ? 1 : 0;
    __syncthreads();
    if (isLast) {
        __threadfence();
        __shared__ double part[NB*NC];
        if (tid < NB*NC) {
            double             v = atomicAdd(&g_num[tid], 0.0);
            unsigned long long c = atomicAdd(&g_cnt[tid], 0ULL);
            part[tid] = (c > 0ULL) ? v / ((double)NC * (double)c) : 0.0;
            g_num[tid] = 0.0;                 // reset for next replay
            g_cnt[tid] = 0ULL;
        }
        __syncthreads();
        if (tid == 0) {
            double loss = 0.0;
#pragma unroll
            for (int j = 0; j < NB*NC; ++j) loss += part[j];
            out[0] = (float)loss;
            g_done = 0u;
        }
    }
}

extern "C" void kernel_launch(void* const* d_in, const int* in_sizes, int n_in,
                              void* d_out, int out_size)
{
    (void)in_sizes; (void)n_in; (void)out_size;
    const float* pS  = (const float*)d_in[0];
    const float* pT  = (const float*)d_in[1];
    const int*   lab = (const int*)  d_in[2];

    dim3 blk(24, 8, 1);
    dim3 grid(1, WW/TW, (HH/HCH)*NB);   // (1, 12, 48) = 576 blocks
    bkd_kernel<<<grid, blk>>>(pS, pT, lab, (float*)d_out);
}

// round 17
// speedup vs baseline: 1.1032x; 1.1032x over previous
#include <cuda_runtime.h>
#include <stdint.h>

// Problem constants
#define NC   14
#define NB   2
#define HH   96
#define WW   96
#define DDim 96
#define CS   (HH*WW*DDim)      // class stride = 884736
#define CS2  (CS/2)
#define ROW  (WW*DDim)         // 9216 floats per h-slice

// Tiling: block (48,8) = 384 threads, 2 voxels/thread, TD = full d-extent (96)
#define TD   96
#define TW   8
#define HCH  8
#define NS   (HCH+2)           // 10 label slices resident
#define SW   (TW+2)            // 10
#define SD   (TD+2)            // 98 shorts per row (even -> rows 4B-aligned)
#define SDU  49                // uints per row
#define CELLS (SW*SD)          // 980 shorts per slice
#define CELLSU (CELLS/2)       // 490 uints per slice
#define GRID_TOTAL 288

typedef unsigned long long u64;

__device__ double             g_num[NB*NC];
__device__ unsigned long long g_cnt[NB*NC];
__device__ unsigned           g_done;

__device__ __forceinline__ void l1_prefetch(const void* p) {
    asm volatile("prefetch.global.L1 [%0];" :: "l"(p));
}
__device__ __forceinline__ u64 pk2(float a, float b) {
    u64 r;
    asm("mov.b64 %0, {%1, %2};" : "=l"(r) : "f"(a), "f"(b));
    return r;
}
__device__ __forceinline__ float2 upk2(u64 v) {
    float2 r;
    asm("mov.b64 {%0, %1}, %2;" : "=f"(r.x), "=f"(r.y) : "l"(v));
    return r;
}
__device__ __forceinline__ float ex2a(float x) {
    float r;
    asm("ex2.approx.f32 %0, %1;" : "=f"(r) : "f"(x));
    return r;
}
#define MUL2(d,a,b)   asm("mul.rn.f32x2 %0, %1, %2;" : "=l"(d) : "l"(a), "l"(b))
#define ADD2(d,a,b)   asm("add.rn.f32x2 %0, %1, %2;" : "=l"(d) : "l"(a), "l"(b))
#define FMA2(d,a,b,c) asm("fma.rn.f32x2 %0, %1, %2, %3;" : "=l"(d) : "l"(a), "l"(b), "l"(c))

__global__ void __launch_bounds__(384, 2) bkd_kernel(
    const float* __restrict__ pS,
    const float* __restrict__ pT,
    const int*   __restrict__ lab,
    float*       __restrict__ out)
{
    const int tx  = threadIdx.x;          // 0..47 (d pair)
    const int ty  = threadIdx.y;          // 0..7  (w)
    const int tid = ty*48 + tx;
    const int w0  = blockIdx.y * TW;
    const int bz  = blockIdx.z;           // 0..23
    const int b   = bz & 1;
    const int h0  = (bz >> 1) * HCH;

    __shared__ unsigned short sm[NS*CELLS];     // 19600 B
    __shared__ int s_is32;

    // ---- label dtype detection (int64 vs int32 layout)
    if (tid == 0) s_is32 = 0;
    __syncthreads();
    if (tid < 128) {
        int odd = lab[2*tid + 1] | lab[2*tid + 257];
        unsigned bal = __ballot_sync(0xffffffffu, odd != 0);
        if (bal && (tid & 31) == 0) atomicOr(&s_is32, 1);
    }
    __syncthreads();
    const int shift = s_is32 ? 0 : 1;

    // ---- prologue: load ALL label slices for this chunk into smem
    for (int c = tid; c < NS*CELLS; c += 384) {
        int sl  = c / CELLS;
        int rem = c - sl*CELLS;
        int wi  = rem / SD;
        int di  = rem - wi*SD;
        int gh = h0 - 1 + sl, gw = w0 - 1 + wi, gd = di - 1;
        unsigned short v = 0;
        if ((unsigned)gh < HH && (unsigned)gw < WW && (unsigned)gd < DDim) {
            int L = __ldg(lab + ((((b*HH + gh)*WW + gw)*DDim + gd) << shift));
            v = (unsigned short)(1u << L);
        }
        sm[c] = v;
    }
    __syncthreads();

    const int dv0 = 2*tx;
    const int w   = w0 + ty;
    const unsigned* smu = (const unsigned*)sm;

    float    acc[NC];
    unsigned cntp[4];                     // 8-bit fields, classes 4j..4j+3
#pragma unroll
    for (int k = 0; k < NC; ++k) acc[k] = 0.f;
#pragma unroll
    for (int j = 0; j < 4; ++j) cntp[j] = 0u;

    const bool w_in = (w >= 1) && (w <= WW-2);
    const bool di0  = (dv0 >= 1);                       // dv0 <= 94 always
    const bool di1  = (dv0+1 <= DDim-2);                // tx=47 -> false

    // hoisted streaming base (advance by ROW floats per h-step)
    const float2* ps2 = (const float2*)(pS + ((b*NC*HH + h0)*WW + w)*DDim + dv0);
    const float2* pt2 = (const float2*)(pT + ((b*NC*HH + h0)*WW + w)*DDim + dv0);

    const u64 L2E2 = pk2(1.4426950408889634f, 1.4426950408889634f);

    for (int i = 0; i < HCH; ++i) {
        const int h = h0 + i;

        // ---- L1 prefetch next h-step's 28 streams (distance-1)
        if (i < HCH - 1) {
#pragma unroll
            for (int c = 0; c < NC; ++c) {
                l1_prefetch(ps2 + c*CS2 + ROW/2);
                l1_prefetch(pt2 + c*CS2 + ROW/2);
            }
        }

        // ---- KL over classes for 2 voxels, packed f32x2 math
        u64 sS2 = 0ull, sT2 = 0ull, nn2 = 0ull, mm2 = 0ull;   // (0.0f,0.0f) pairs
#pragma unroll
        for (int c = 0; c < NC; ++c) {
            float2 sf = __ldcs(ps2 + c*CS2);
            float2 tf = __ldcs(pt2 + c*CS2);
            u64 s = pk2(sf.x, sf.y);
            u64 t = pk2(tf.x, tf.y);
            u64 tl; MUL2(tl, t, L2E2);
            float2 tlu = upk2(tl);
            u64 e = pk2(ex2a(tlu.x), ex2a(tlu.y));
            ADD2(sT2, sT2, e);
            FMA2(nn2, e, t, nn2);
            FMA2(mm2, e, s, mm2);
            u64 sl; MUL2(sl, s, L2E2);
            float2 slu = upk2(sl);
            u64 f = pk2(ex2a(slu.x), ex2a(slu.y));
            ADD2(sS2, sS2, f);
        }
        float2 sT = upk2(sT2), sS = upk2(sS2), nn = upk2(nn2), mm = upk2(mm2);
        float r0 = __fdividef(1.f, sT.x), r1 = __fdividef(1.f, sT.y);
        float kl0 = fmaf(nn.x - mm.x, r0, __logf(sS.x * r0));
        float kl1 = fmaf(nn.y - mm.y, r1, __logf(sS.y * r1));
        ps2 += ROW/2;
        pt2 += ROW/2;

        // ---- 26-neighbor presence masks, aligned uint32 window reads
        unsigned A0=0, A1=0, C0, C1;
#pragma unroll
        for (int r = 0; r < 3; ++r) {
            const unsigned* p = smu + i*CELLSU + (ty + r)*SDU + tx;   // slice h-1
            A0 |= p[0]; A1 |= p[1];
            const unsigned* q = p + 2*CELLSU;                          // slice h+1
            A0 |= q[0]; A1 |= q[1];
        }
        {
            const unsigned* p = smu + (i+1)*CELLSU + ty*SDU + tx;      // slice h, row w-1
            A0 |= p[0]; A1 |= p[1];
            const unsigned* q = p + 2*SDU;                             // row w+1
            A0 |= q[0]; A1 |= q[1];
            const unsigned* cc = p + SDU;                              // center row
            C0 = cc[0]; C1 = cc[1];
        }
        unsigned a0=A0&0xffffu, a1=A0>>16, a2=A1&0xffffu, a3=A1>>16;
        unsigned c0=C0&0xffffu, c1=C0>>16, c2=C1&0xffffu, c3=C1>>16;
        unsigned m0 = a0|a1|a2|c0|c2;      // center voxel0 (c1) excluded
        unsigned m1 = a1|a2|a3|c1|c3;      // center voxel1 (c2) excluded

        const bool hw = w_in && (h >= 1) && (h <= HH-2);
        unsigned bm0 = (hw && di0 && ((m0&(m0-1u))==0u)) ? 0u : m0;
        unsigned bm1 = (hw && di1 && ((m1&(m1-1u))==0u)) ? 0u : m1;

#pragma unroll
        for (int k = 0; k < NC; ++k) {
            const unsigned bit = 1u << k;
            const unsigned fld = 1u << (8*(k & 3));
            if (bm0 & bit) { acc[k] += kl0; cntp[k >> 2] += fld; }
            if (bm1 & bit) { acc[k] += kl1; cntp[k >> 2] += fld; }
        }
    }

    // ---- expand 8-bit counters (max 16 < 255), then warp-reduce
    int cnt[NC];
#pragma unroll
    for (int k = 0; k < NC; ++k)
        cnt[k] = (int)((cntp[k >> 2] >> (8*(k & 3))) & 0xffu);

#pragma unroll
    for (int k = 0; k < NC; ++k) {
        float a = acc[k]; int c = cnt[k];
#pragma unroll
        for (int off = 16; off; off >>= 1) {
            a += __shfl_xor_sync(0xffffffffu, a, off);
            c += __shfl_xor_sync(0xffffffffu, c, off);
        }
        acc[k] = a; cnt[k] = c;
    }

    __shared__ float rf[NC];
    __shared__ int   ri[NC];
    if (tid < NC) { rf[tid] = 0.f; ri[tid] = 0; }
    __syncthreads();
    if ((tid & 31) == 0) {
#pragma unroll
        for (int k = 0; k < NC; ++k) {
            atomicAdd(&rf[k], acc[k]);
            atomicAdd(&ri[k], cnt[k]);
        }
    }
    __syncthreads();
    if (tid < NC) {
        atomicAdd(&g_num[b*NC + tid], (double)rf[tid]);
        atomicAdd(&g_cnt[b*NC + tid], (unsigned long long)ri[tid]);
    }

    // ---- last-block finalize (fused epilogue)
    __threadfence();
    __shared__ int isLast;
    if (tid == 0) isLast = (atomicAdd(&g_done, 1u) == GRID_TOTAL - 1u) ? 1 : 0;
    __syncthreads();
    if (isLast) {
        __threadfence();
        __shared__ double part[NB*NC];
        if (tid < NB*NC) {
            double             v = atomicAdd(&g_num[tid], 0.0);
            unsigned long long c = atomicAdd(&g_cnt[tid], 0ULL);
            part[tid] = (c > 0ULL) ? v / ((double)NC * (double)c) : 0.0;
            g_num[tid] = 0.0;                 // reset for next replay
            g_cnt[tid] = 0ULL;
        }
        __syncthreads();
        if (tid == 0) {
            double loss = 0.0;
#pragma unroll
            for (int j = 0; j < NB*NC; ++j) loss += part[j];
            out[0] = (float)loss;
            g_done = 0u;
        }
    }
}

extern "C" void kernel_launch(void* const* d_in, const int* in_sizes, int n_in,
                              void* d_out, int out_size)
{
    (void)in_sizes; (void)n_in; (void)out_size;
    const float* pS  = (const float*)d_in[0];
    const float* pT  = (const float*)d_in[1];
    const int*   lab = (const int*)  d_in[2];

    dim3 blk(48, 8, 1);
    dim3 grid(1, WW/TW, (HH/HCH)*NB);   // (1, 12, 24) = 288 blocks
    bkd_kernel<<<grid, blk>>>(pS, pT, lab, (float*)d_out);
}